// round 1
// baseline (speedup 1.0000x reference)
#include <cuda_runtime.h>
#include <math.h>

// Problem shape (fixed by the reference): N=4, T=4096, D=Q=V=1024.
#define NBATCH 4
#define SEQ    4096
#define DIM    1024

// Scratch: q,k,v (64 MB each) + scores (256 MB). Static __device__ arrays
// (allocation inside kernel_launch is forbidden).
__device__ float g_q[(size_t)NBATCH * SEQ * DIM];
__device__ float g_k[(size_t)NBATCH * SEQ * DIM];
__device__ float g_v[(size_t)NBATCH * SEQ * DIM];
__device__ float g_s[(size_t)NBATCH * SEQ * SEQ];

// ---------------------------------------------------------------------------
// Classic 128x128x16 SGEMM, 256 threads, 8x8 register tile per thread.
//   C[m][n] = alpha * sum_k A[m][k] * op(B)[k][n]  (+ bias[n])
// B_KMAJOR=true : B stored [N][K] row-major (i.e. C = A * B^T)   -- X*W^T, Q*K^T
// B_KMAJOR=false: B stored [K][N] row-major (i.e. C = A * B)     -- Attn*V
// All dims here are multiples of the tile sizes, so no bounds checks.
// ---------------------------------------------------------------------------
constexpr int BM = 128, BN = 128, BK = 16, TM = 8, TN = 8;

template <bool B_KMAJOR, bool HAS_BIAS>
__global__ void __launch_bounds__(256)
sgemm_kernel(const float* __restrict__ Ab, const float* __restrict__ Bb,
             const float* __restrict__ bias, float* __restrict__ Cb,
             int M, int N, int K,
             size_t strideA, size_t strideB, size_t strideC, float alpha)
{
    const float* A = Ab + (size_t)blockIdx.z * strideA;
    const float* B = Bb + (size_t)blockIdx.z * strideB;
    float*       C = Cb + (size_t)blockIdx.z * strideC;

    __shared__ float As[BK][BM];
    __shared__ float Bs[BK][BN];

    const int tid = threadIdx.x;
    const int tx  = tid & 15;        // 16 thread columns
    const int ty  = tid >> 4;        // 16 thread rows
    const int m0  = blockIdx.y * BM;
    const int n0  = blockIdx.x * BN;

    float acc[TM][TN];
#pragma unroll
    for (int i = 0; i < TM; i++)
#pragma unroll
        for (int j = 0; j < TN; j++) acc[i][j] = 0.0f;

    for (int k0 = 0; k0 < K; k0 += BK) {
        // --- load A tile (BM x BK), stored transposed in shared ---
#pragma unroll
        for (int l = 0; l < 2; l++) {
            int v   = tid + 256 * l;          // 512 float4 loads total
            int row = v >> 2;                 // 0..127
            int c4  = (v & 3) * 4;            // 0,4,8,12
            float4 a = *reinterpret_cast<const float4*>(
                &A[(size_t)(m0 + row) * K + k0 + c4]);
            As[c4 + 0][row] = a.x;
            As[c4 + 1][row] = a.y;
            As[c4 + 2][row] = a.z;
            As[c4 + 3][row] = a.w;
        }
        // --- load B tile ---
        if (B_KMAJOR) {
#pragma unroll
            for (int l = 0; l < 2; l++) {
                int v   = tid + 256 * l;
                int row = v >> 2;             // n-index within tile
                int c4  = (v & 3) * 4;        // k-offset
                float4 b = *reinterpret_cast<const float4*>(
                    &B[(size_t)(n0 + row) * K + k0 + c4]);
                Bs[c4 + 0][row] = b.x;
                Bs[c4 + 1][row] = b.y;
                Bs[c4 + 2][row] = b.z;
                Bs[c4 + 3][row] = b.w;
            }
        } else {
#pragma unroll
            for (int l = 0; l < 2; l++) {
                int v   = tid + 256 * l;
                int row = v >> 5;             // 0..15 (k within tile)
                int c4  = (v & 31) * 4;       // 0..124 (n within tile)
                *reinterpret_cast<float4*>(&Bs[row][c4]) =
                    *reinterpret_cast<const float4*>(
                        &B[(size_t)(k0 + row) * N + n0 + c4]);
            }
        }
        __syncthreads();

        // --- FMA over this K-slab ---
#pragma unroll
        for (int kk = 0; kk < BK; kk++) {
            float a[TM], b[TN];
            *reinterpret_cast<float4*>(&a[0]) =
                *reinterpret_cast<const float4*>(&As[kk][ty * TM]);
            *reinterpret_cast<float4*>(&a[4]) =
                *reinterpret_cast<const float4*>(&As[kk][ty * TM + 4]);
            *reinterpret_cast<float4*>(&b[0]) =
                *reinterpret_cast<const float4*>(&Bs[kk][tx * TN]);
            *reinterpret_cast<float4*>(&b[4]) =
                *reinterpret_cast<const float4*>(&Bs[kk][tx * TN + 4]);
#pragma unroll
            for (int i = 0; i < TM; i++)
#pragma unroll
                for (int j = 0; j < TN; j++)
                    acc[i][j] = fmaf(a[i], b[j], acc[i][j]);
        }
        __syncthreads();
    }

    // --- epilogue: alpha scale + optional bias, vectorized stores ---
    float bcol[TN];
#pragma unroll
    for (int j = 0; j < TN; j++)
        bcol[j] = HAS_BIAS ? bias[n0 + tx * TN + j] : 0.0f;

#pragma unroll
    for (int i = 0; i < TM; i++) {
        float* cp = &C[(size_t)(m0 + ty * TM + i) * N + n0 + tx * TN];
        float4 r0, r1;
        r0.x = fmaf(alpha, acc[i][0], bcol[0]);
        r0.y = fmaf(alpha, acc[i][1], bcol[1]);
        r0.z = fmaf(alpha, acc[i][2], bcol[2]);
        r0.w = fmaf(alpha, acc[i][3], bcol[3]);
        r1.x = fmaf(alpha, acc[i][4], bcol[4]);
        r1.y = fmaf(alpha, acc[i][5], bcol[5]);
        r1.z = fmaf(alpha, acc[i][6], bcol[6]);
        r1.w = fmaf(alpha, acc[i][7], bcol[7]);
        *reinterpret_cast<float4*>(cp)     = r0;
        *reinterpret_cast<float4*>(cp + 4) = r1;
    }
}

// ---------------------------------------------------------------------------
// Row softmax over 4096-wide rows. One block (256 threads) per row,
// 16 elements per thread, in registers.
// ---------------------------------------------------------------------------
__global__ void __launch_bounds__(256) softmax_kernel(float* __restrict__ S)
{
    float* p = S + (size_t)blockIdx.x * SEQ;
    const int t = threadIdx.x;

    float v[16];
    float m = -1e30f;
#pragma unroll
    for (int i = 0; i < 16; i++) {
        v[i] = p[t + 256 * i];
        m = fmaxf(m, v[i]);
    }

    __shared__ float redmax[8];
    __shared__ float redsum[8];
#pragma unroll
    for (int o = 16; o > 0; o >>= 1)
        m = fmaxf(m, __shfl_xor_sync(0xffffffffu, m, o));
    if ((t & 31) == 0) redmax[t >> 5] = m;
    __syncthreads();
    m = redmax[0];
#pragma unroll
    for (int w = 1; w < 8; w++) m = fmaxf(m, redmax[w]);

    float sum = 0.0f;
#pragma unroll
    for (int i = 0; i < 16; i++) {
        v[i] = __expf(v[i] - m);
        sum += v[i];
    }
#pragma unroll
    for (int o = 16; o > 0; o >>= 1)
        sum += __shfl_xor_sync(0xffffffffu, sum, o);
    if ((t & 31) == 0) redsum[t >> 5] = sum;
    __syncthreads();
    sum = 0.0f;
#pragma unroll
    for (int w = 0; w < 8; w++) sum += redsum[w];

    const float inv = 1.0f / sum;
#pragma unroll
    for (int i = 0; i < 16; i++) p[t + 256 * i] = v[i] * inv;
}

// ---------------------------------------------------------------------------
// Launch: 3 projection GEMMs -> scores GEMM -> softmax -> A*V GEMM.
// All on the capture stream; sequential launches give the needed ordering.
// ---------------------------------------------------------------------------
extern "C" void kernel_launch(void* const* d_in, const int* in_sizes, int n_in,
                              void* d_out, int out_size)
{
    const float* X  = (const float*)d_in[0];
    const float* Wq = (const float*)d_in[1];
    const float* bq = (const float*)d_in[2];
    const float* Wk = (const float*)d_in[3];
    const float* bk = (const float*)d_in[4];
    const float* Wv = (const float*)d_in[5];
    const float* bv = (const float*)d_in[6];
    float* out = (float*)d_out;

    float *q, *k, *v, *s;
    cudaGetSymbolAddress((void**)&q, g_q);
    cudaGetSymbolAddress((void**)&k, g_k);
    cudaGetSymbolAddress((void**)&v, g_v);
    cudaGetSymbolAddress((void**)&s, g_s);

    const int M = NBATCH * SEQ;  // 16384 rows for the fused projections
    dim3 blk(256);

    // Projections: C = X * W^T + b   (M x 1024, K = 1024)
    dim3 gp(DIM / BN, M / BM, 1);  // (8, 128)
    sgemm_kernel<true, true><<<gp, blk>>>(X, Wq, bq, q, M, DIM, DIM, 0, 0, 0, 1.0f);
    sgemm_kernel<true, true><<<gp, blk>>>(X, Wk, bk, k, M, DIM, DIM, 0, 0, 0, 1.0f);
    sgemm_kernel<true, true><<<gp, blk>>>(X, Wv, bv, v, M, DIM, DIM, 0, 0, 0, 1.0f);

    // Scores: S = (Q * K^T) / sqrt(1024), per batch
    dim3 gs(SEQ / BN, SEQ / BM, NBATCH);  // (32, 32, 4)
    sgemm_kernel<true, false><<<gs, blk>>>(
        q, k, nullptr, s, SEQ, SEQ, DIM,
        (size_t)SEQ * DIM, (size_t)SEQ * DIM, (size_t)SEQ * SEQ, 1.0f / 32.0f);

    // Row softmax over all NBATCH*SEQ rows
    softmax_kernel<<<NBATCH * SEQ, 256>>>(s);

    // Output: O = Attn * V, per batch
    dim3 ga(DIM / BN, SEQ / BM, NBATCH);  // (8, 32, 4)
    sgemm_kernel<false, false><<<ga, blk>>>(
        s, v, nullptr, out, SEQ, DIM, SEQ,
        (size_t)SEQ * SEQ, (size_t)SEQ * DIM, (size_t)SEQ * DIM, 1.0f);
}